// round 6
// baseline (speedup 1.0000x reference)
#include <cuda_runtime.h>
#include <cstdint>

#define THREADS 256

// Chunk = 8 rows; group = 32 chunks = 256 rows.
// P[b][g][k][c] = per-channel sum of chunks [32g, 32g+k) of batch b (k in 0..32).
__device__ float g_p0[8][64][33][128];   // tensor0: T=16384 -> 2048 chunks, 64 groups (8.7 MB)
__device__ float g_p1[8][32][33][128];   // tensor1: T=8192  -> 1024 chunks, 32 groups (4.3 MB)
__device__ float g_p2[8][16][33][256];   // tensor2: T=4096  ->  512 chunks, 16 groups (4.3 MB)

__device__ __forceinline__ void add4(float4& a, const float4 x) {
    a.x += x.x; a.y += x.y; a.z += x.z; a.w += x.w;
}
__device__ __forceinline__ float4 sub4(const float4 a, const float4 b) {
    return make_float4(a.x - b.x, a.y - b.y, a.z - b.z, a.w - b.w);
}

// ---------------- K1: grouped chunk sums + in-block local prefix ----------------
template<int T, int VEC, int NG>
__device__ __forceinline__ void build_prefix(const float* __restrict__ v,
                                             float* __restrict__ P,
                                             int b, int g, float4* __restrict__ smem)
{
    constexpr int NACC = VEC / 32;        // 1 (C=128) or 2 (C=256)
    const int warp = threadIdx.x >> 5;
    const int lane = threadIdx.x & 31;

    const float4* src = (const float4*)v + ((size_t)b * T + (size_t)g * 256) * VEC + lane;
#pragma unroll
    for (int c = 0; c < 4; c++) {         // 4 chunks per warp
        const int chunk = warp * 4 + c;
        float4 a[NACC];
#pragma unroll
        for (int j = 0; j < NACC; j++) a[j] = make_float4(0.f, 0.f, 0.f, 0.f);
        const float4* p = src + (size_t)chunk * 8 * VEC;
#pragma unroll
        for (int r = 0; r < 8; r++)
#pragma unroll
            for (int j = 0; j < NACC; j++) add4(a[j], __ldg(p + r * VEC + j * 32));
#pragma unroll
        for (int j = 0; j < NACC; j++) smem[chunk * VEC + j * 32 + lane] = a[j];
    }
    __syncthreads();

    if (warp == 0) {                      // serial 32-step scan, one warp
        float4* Pg = (float4*)P + (size_t)(b * NG + g) * 33 * VEC + lane;
        float4 run[NACC];
#pragma unroll
        for (int j = 0; j < NACC; j++) {
            run[j] = make_float4(0.f, 0.f, 0.f, 0.f);
            Pg[j * 32] = run[j];          // P[...][0] = 0
        }
        for (int k = 0; k < 32; k++) {
#pragma unroll
            for (int j = 0; j < NACC; j++) {
                add4(run[j], smem[k * VEC + j * 32 + lane]);
                Pg[(k + 1) * VEC + j * 32] = run[j];
            }
        }
    }
}

__global__ void __launch_bounds__(THREADS)
prefix_kernel(const float* __restrict__ v0, const float* __restrict__ v1,
              const float* __restrict__ v2)
{
    __shared__ float4 smem[2048];         // 32 KB (t2 uses all; t0/t1 use half)
    const int blk = blockIdx.x;
    if (blk < 512) {
        build_prefix<16384, 32, 64>(v0, (float*)g_p0, blk >> 6, blk & 63, smem);
    } else if (blk < 768) {
        const int i = blk - 512;
        build_prefix<8192, 32, 32>(v1, (float*)g_p1, i >> 5, i & 31, smem);
    } else {
        const int i = blk - 768;
        build_prefix<4096, 64, 16>(v2, (float*)g_p2, i >> 4, i & 15, smem);
    }
}

// ---------------- K2: per-query gather (O(1) interior + ragged edges) ----------------
template<int T, int VEC, int NG, int CHOFF>
__device__ __forceinline__ void gather_one(
    const float* __restrict__ v, const float* __restrict__ P,
    float ratio, const float* __restrict__ start, const float* __restrict__ dur,
    float* __restrict__ out, int q, int lane)
{
    constexpr int NACC = VEC / 32;
    const int b = q >> 9;
    const float st = start[q];
    const float du = dur[q];
    // Match reference fp32 op order exactly.
    int s = (int)floorf(st * ratio);
    if (s > T - 1) s = T - 1;
    int e = (int)ceilf((st + du + 1e-3f) * ratio);
    if (e > T - 1) e = T - 1;
    const int cnt = e - s;

    float4 acc[NACC];
#pragma unroll
    for (int j = 0; j < NACC; j++) acc[j] = make_float4(0.f, 0.f, 0.f, 0.f);

    if (cnt > 0) {
        const float4* vb = (const float4*)v + (size_t)b * T * VEC + lane;
        const int cLo = (s + 7) >> 3;
        const int cHi = e >> 3;
        if (cLo <= cHi) {
            const float4* Pb = (const float4*)P + (size_t)b * NG * 33 * VEC + lane;
            const int g0 = cLo >> 5, k0 = cLo & 31;
            const int g1 = cHi >> 5, k1 = cHi & 31;
#pragma unroll
            for (int j = 0; j < NACC; j++)
                acc[j] = sub4(__ldg(Pb + (g1 * 33 + k1) * VEC + j * 32),
                              __ldg(Pb + (g0 * 33 + k0) * VEC + j * 32));
            for (int g = g0; g < g1; g++)           // <=2 iterations
#pragma unroll
                for (int j = 0; j < NACC; j++)
                    add4(acc[j], __ldg(Pb + (g * 33 + 32) * VEC + j * 32));
            // ragged edges: [s, 8*cLo) and [8*cHi, e), each <=7 rows
            const int eL = cLo << 3, sR = cHi << 3;
            for (int r = s; r < eL; r++)
#pragma unroll
                for (int j = 0; j < NACC; j++)
                    add4(acc[j], __ldg(vb + (size_t)r * VEC + j * 32));
            for (int r = sR; r < e; r++)
#pragma unroll
                for (int j = 0; j < NACC; j++)
                    add4(acc[j], __ldg(vb + (size_t)r * VEC + j * 32));
        } else {
            // whole range inside one chunk (<8 rows)
            for (int r = s; r < e; r++)
#pragma unroll
                for (int j = 0; j < NACC; j++)
                    add4(acc[j], __ldg(vb + (size_t)r * VEC + j * 32));
        }
        const float inv = 1.0f / (float)cnt;
#pragma unroll
        for (int j = 0; j < NACC; j++) {
            acc[j].x *= inv; acc[j].y *= inv; acc[j].z *= inv; acc[j].w *= inv;
        }
    }
    float4* op = (float4*)(out + (size_t)q * 512 + CHOFF) + lane;
#pragma unroll
    for (int j = 0; j < NACC; j++) op[j * 32] = acc[j];
}

__global__ void __launch_bounds__(THREADS)
gather_kernel(const float* __restrict__ v0, const float* __restrict__ v1,
              const float* __restrict__ v2,
              const float* __restrict__ start, const float* __restrict__ dur,
              float* __restrict__ out)
{
    const int wg   = blockIdx.x * (THREADS / 32) + (threadIdx.x >> 5); // 0..12287
    const int lane = threadIdx.x & 31;
    const int tensor = wg >> 12;
    const int q      = wg & 4095;

    if (tensor == 0) {
        gather_one<16384, 32, 64, 0>(v0, (const float*)g_p0, 1.0f, start, dur, out, q, lane);
    } else if (tensor == 1) {
        gather_one<8192, 32, 32, 128>(v1, (const float*)g_p1, 0.5f, start, dur, out, q, lane);
    } else {
        gather_one<4096, 64, 16, 256>(v2, (const float*)g_p2, 0.25f, start, dur, out, q, lane);
    }
}

extern "C" void kernel_launch(void* const* d_in, const int* in_sizes, int n_in,
                              void* d_out, int out_size) {
    const float* v0 = (const float*)d_in[0];  // [8, 16384, 128]
    const float* v1 = (const float*)d_in[1];  // [8, 8192, 128]
    const float* v2 = (const float*)d_in[2];  // [8, 4096, 256]
    const float* st = (const float*)d_in[3];  // [8, 512]
    const float* du = (const float*)d_in[4];  // [8, 512]
    float* out = (float*)d_out;               // [8, 512, 512]

    prefix_kernel<<<896, THREADS>>>(v0, v1, v2);
    gather_kernel<<<1536, THREADS>>>(v0, v1, v2, st, du, out);
}